// round 5
// baseline (speedup 1.0000x reference)
#include <cuda_runtime.h>
#include <math.h>

// ---------------------------------------------------------------------------
// VQ-VAE forward, fp32 baseline.
// Pipeline: enc1 -> enc2 -> [enc3 + VQ argmin + quantize, fused] -> dec1 ->
//           [dec2 + dec3, fused] -> finalize (vq_loss, perplexity).
// ---------------------------------------------------------------------------

#define NR   262144          // rows
#define GRID (NR / 64)       // 4096 blocks of 64 rows

// Scratch (static device memory — no allocation anywhere)
__device__ float g_h1[NR * 256];   // 256 MB : enc1 out
__device__ float g_h2[NR * 128];   // 128 MB : enc2 out, reused as dec1 out
__device__ float g_q [NR * 64];    //  64 MB : quantized latents
__device__ float g_hn[1024];       // 0.5*||codebook_j||^2
__device__ int   g_hist[1024];     // codebook usage counts
__device__ float g_msep[GRID];     // per-block sum of (q - z)^2

// ---------------------------------------------------------------------------
__global__ void k_init() { g_hist[threadIdx.x] = 0; }

__global__ void k_hn(const float* __restrict__ cb) {
    int j = blockIdx.x * 256 + threadIdx.x;   // grid 4 x 256
    float s = 0.f;
    #pragma unroll 8
    for (int d = 0; d < 64; d++) { float v = cb[j * 64 + d]; s = fmaf(v, v, s); }
    g_hn[j] = 0.5f * s;
}

// ---------------------------------------------------------------------------
// enc1: [N,9] -> relu -> [N,256].  Memory-bound; one col per thread (mod 256).
__global__ __launch_bounds__(512, 1)
void k_enc1(const float* __restrict__ X, const float* __restrict__ W,
            const float* __restrict__ B, float* __restrict__ out) {
    __shared__ float xs[64 * 12];
    int tid = threadIdx.x;
    long row0 = (long)blockIdx.x * 64;
    for (int i = tid; i < 64 * 9; i += 512) {
        int r = i / 9, k = i - r * 9;
        xs[r * 12 + k] = X[row0 * 9 + i];
    }
    int col = tid & 255;
    int rh  = tid >> 8;
    float w[9];
    float b = __ldg(&B[col]);
    #pragma unroll
    for (int k = 0; k < 9; k++) w[k] = __ldg(&W[col * 9 + k]);
    __syncthreads();
    for (int r = rh * 32; r < rh * 32 + 32; r++) {
        float acc = b;
        #pragma unroll
        for (int k = 0; k < 9; k++) acc = fmaf(xs[r * 12 + k], w[k], acc);
        out[(row0 + r) * 256 + col] = fmaxf(acc, 0.f);
    }
}

// ---------------------------------------------------------------------------
// Generic MLP layer: out[64-row tile, DOUT] = (relu)(A @ W^T + B)
// 512 threads: cg = tid&15 (16 col groups, cols strided by 16), rg = tid>>4
// (32 row groups of 2 rows). Smem stride DIN+1 => bank-conflict-free W reads.
template <int DIN, int DOUT, bool RELU>
__global__ __launch_bounds__(512, 1)
void k_mlp(const float* __restrict__ A, const float* __restrict__ W,
           const float* __restrict__ B, float* __restrict__ out) {
    constexpr int TM = 64, DP = DIN + 1, CPT = DOUT / 16;
    extern __shared__ float sm[];
    float* As = sm;                 // TM * DP
    float* Ws = sm + TM * DP;       // DOUT * DP
    int tid = threadIdx.x;
    long row0 = (long)blockIdx.x * TM;
    for (int i = tid; i < TM * DIN; i += 512) {
        int r = i / DIN, k = i - r * DIN;
        As[r * DP + k] = A[row0 * DIN + i];
    }
    for (int i = tid; i < DOUT * DIN; i += 512) {
        int c = i / DIN, k = i - c * DIN;
        Ws[c * DP + k] = W[i];
    }
    __syncthreads();
    int cg = tid & 15, rg = tid >> 4;
    float acc[2][CPT];
    #pragma unroll
    for (int j = 0; j < CPT; j++) {
        float b = __ldg(&B[cg + 16 * j]);
        acc[0][j] = b; acc[1][j] = b;
    }
    const float* ap = As + (rg * 2) * DP;
    const float* wp = Ws + cg * DP;
    #pragma unroll 4
    for (int k = 0; k < DIN; k++) {
        float a0 = ap[k], a1 = ap[DP + k];
        #pragma unroll
        for (int j = 0; j < CPT; j++) {
            float w = wp[j * 16 * DP + k];
            acc[0][j] = fmaf(a0, w, acc[0][j]);
            acc[1][j] = fmaf(a1, w, acc[1][j]);
        }
    }
    #pragma unroll
    for (int r = 0; r < 2; r++)
        #pragma unroll
        for (int j = 0; j < CPT; j++) {
            float v = acc[r][j];
            if (RELU) v = fmaxf(v, 0.f);
            out[(row0 + rg * 2 + r) * DOUT + cg + 16 * j] = v;
        }
}

// ---------------------------------------------------------------------------
// Fused enc3 + VQ: h2 tile -> z tile (smem) -> argmax(z.c - 0.5|c|^2) over
// 1024 codes in 8 tiles of 128 -> histogram, quantized gather, mse partial.
__global__ __launch_bounds__(512, 1)
void k_vq(const float* __restrict__ H, const float* __restrict__ W3,
          const float* __restrict__ B3, const float* __restrict__ CB,
          float* __restrict__ Q) {
    extern __shared__ float sm[];
    float* hs   = sm;                    // 64*129
    float* w3s  = hs  + 64 * 129;        // 64*129
    float* zs   = w3s + 64 * 129;        // 64*65
    float* cs   = zs  + 64 * 65;         // 128*65
    float* hns  = cs  + 128 * 65;        // 128
    float* red_s = hns + 128;            // 64*16
    int*   red_i = (int*)(red_s + 64 * 16);  // 64*16
    int*   idxs  = red_i + 64 * 16;          // 64
    __shared__ float warr[16];

    int tid = threadIdx.x;
    long row0 = (long)blockIdx.x * 64;
    for (int i = tid; i < 64 * 128; i += 512) {
        int r = i >> 7, k = i & 127;
        hs[r * 129 + k] = H[row0 * 128 + i];
    }
    for (int i = tid; i < 64 * 128; i += 512) {
        int c = i >> 7, k = i & 127;
        w3s[c * 129 + k] = W3[i];
    }
    __syncthreads();

    int cg = tid & 15, rg = tid >> 4;
    // --- phase A: z tile = h2 @ w3^T + b3 (no relu) ---
    {
        float acc[2][4];
        #pragma unroll
        for (int j = 0; j < 4; j++) {
            float b = __ldg(&B3[cg + 16 * j]);
            acc[0][j] = b; acc[1][j] = b;
        }
        const float* ap = hs + (rg * 2) * 129;
        const float* wp = w3s + cg * 129;
        #pragma unroll 4
        for (int k = 0; k < 128; k++) {
            float a0 = ap[k], a1 = ap[129 + k];
            #pragma unroll
            for (int j = 0; j < 4; j++) {
                float w = wp[j * 16 * 129 + k];
                acc[0][j] = fmaf(a0, w, acc[0][j]);
                acc[1][j] = fmaf(a1, w, acc[1][j]);
            }
        }
        #pragma unroll
        for (int r = 0; r < 2; r++)
            #pragma unroll
            for (int j = 0; j < 4; j++)
                zs[(rg * 2 + r) * 65 + cg + 16 * j] = acc[r][j];
    }

    // --- phase B: distance GEMM over 8 code tiles of 128 ---
    float best0 = -3.4e38f, best1 = -3.4e38f;
    int   bi0 = 0, bi1 = 0;
    for (int t = 0; t < 8; t++) {
        __syncthreads();
        for (int i = tid; i < 128 * 64; i += 512) {
            int c = i >> 6, k = i & 63;
            cs[c * 65 + k] = CB[(long)(t * 128) * 64 + i];
        }
        if (tid < 128) hns[tid] = g_hn[t * 128 + tid];
        __syncthreads();
        float acc[2][8];
        #pragma unroll
        for (int j = 0; j < 8; j++) { acc[0][j] = 0.f; acc[1][j] = 0.f; }
        const float* zp = zs + (rg * 2) * 65;
        const float* cp = cs + cg * 65;
        #pragma unroll 4
        for (int k = 0; k < 64; k++) {
            float a0 = zp[k], a1 = zp[65 + k];
            #pragma unroll
            for (int j = 0; j < 8; j++) {
                float w = cp[j * 16 * 65 + k];
                acc[0][j] = fmaf(a0, w, acc[0][j]);
                acc[1][j] = fmaf(a1, w, acc[1][j]);
            }
        }
        #pragma unroll
        for (int j = 0; j < 8; j++) {
            int gi = t * 128 + cg + 16 * j;   // ascending within thread
            float h = hns[cg + 16 * j];
            float s0 = acc[0][j] - h;
            float s1 = acc[1][j] - h;
            if (s0 > best0) { best0 = s0; bi0 = gi; }   // strict > keeps first
            if (s1 > best1) { best1 = s1; bi1 = gi; }
        }
    }

    // --- phase C: cross-colgroup reduce (tie -> smallest index) ---
    red_s[(rg * 2 + 0) * 16 + cg] = best0; red_i[(rg * 2 + 0) * 16 + cg] = bi0;
    red_s[(rg * 2 + 1) * 16 + cg] = best1; red_i[(rg * 2 + 1) * 16 + cg] = bi1;
    __syncthreads();
    if (tid < 64) {
        float bs = red_s[tid * 16];
        int   bi = red_i[tid * 16];
        #pragma unroll
        for (int c = 1; c < 16; c++) {
            float s = red_s[tid * 16 + c];
            int  ii = red_i[tid * 16 + c];
            if (s > bs || (s == bs && ii < bi)) { bs = s; bi = ii; }
        }
        idxs[tid] = bi;
        atomicAdd(&g_hist[bi], 1);
    }
    __syncthreads();

    // --- phase D: gather quantized rows, accumulate mse partial ---
    float lsum = 0.f;
    for (int i = tid; i < 64 * 64; i += 512) {
        int r = i >> 6, d = i & 63;
        int ci = idxs[r];
        float q = __ldg(&CB[(long)ci * 64 + d]);
        float z = zs[r * 65 + d];
        Q[row0 * 64 + i] = q;
        float df = q - z;
        lsum = fmaf(df, df, lsum);
    }
    #pragma unroll
    for (int o = 16; o; o >>= 1) lsum += __shfl_xor_sync(0xffffffffu, lsum, o);
    if ((tid & 31) == 0) warr[tid >> 5] = lsum;
    __syncthreads();
    if (tid == 0) {
        float s = 0.f;
        #pragma unroll
        for (int w = 0; w < 16; w++) s += warr[w];   // fixed order: deterministic
        g_msep[blockIdx.x] = s;
    }
}

// ---------------------------------------------------------------------------
// Fused dec2 (128->256, relu) + dec3 (256->9) -> x_recon straight to d_out.
__global__ __launch_bounds__(512, 1)
void k_dec23(const float* __restrict__ A, const float* __restrict__ W2,
             const float* __restrict__ B2, const float* __restrict__ W3,
             const float* __restrict__ B3, float* __restrict__ out) {
    extern __shared__ float sm[];
    float* As  = sm;            // 64*129 = 8256
    float* Ws  = sm + 8256;     // 256*129 = 33024  (ends 41280)
    float* W3s = sm + 41280;    // 9*257 = 2313
    float* d2s = sm;            // 64*260 = 16640, overlays As+Ws head after use
    int tid = threadIdx.x;
    long row0 = (long)blockIdx.x * 64;
    for (int i = tid; i < 64 * 128; i += 512) {
        int r = i >> 7, k = i & 127;
        As[r * 129 + k] = A[row0 * 128 + i];
    }
    for (int i = tid; i < 256 * 128; i += 512) {
        int c = i >> 7, k = i & 127;
        Ws[c * 129 + k] = W2[i];
    }
    for (int i = tid; i < 9 * 256; i += 512) {
        int c = i / 256, k = i - c * 256;
        W3s[c * 257 + k] = W3[i];
    }
    __syncthreads();

    int cg = tid & 15, rg = tid >> 4;
    float acc[2][16];
    #pragma unroll
    for (int j = 0; j < 16; j++) {
        float b = __ldg(&B2[cg + 16 * j]);
        acc[0][j] = b; acc[1][j] = b;
    }
    const float* ap = As + (rg * 2) * 129;
    const float* wp = Ws + cg * 129;
    #pragma unroll 4
    for (int k = 0; k < 128; k++) {
        float a0 = ap[k], a1 = ap[129 + k];
        #pragma unroll
        for (int j = 0; j < 16; j++) {
            float w = wp[j * 16 * 129 + k];
            acc[0][j] = fmaf(a0, w, acc[0][j]);
            acc[1][j] = fmaf(a1, w, acc[1][j]);
        }
    }
    __syncthreads();   // everyone done reading As/Ws before overlay
    #pragma unroll
    for (int r = 0; r < 2; r++)
        #pragma unroll
        for (int j = 0; j < 16; j++)
            d2s[(rg * 2 + r) * 260 + cg + 16 * j] = fmaxf(acc[r][j], 0.f);
    __syncthreads();

    // dec3: 64 rows x 9 cols, K = 256
    for (int e = tid; e < 64 * 9; e += 512) {
        int r = e / 9, c = e - r * 9;
        const float* dp = d2s + r * 260;
        const float* wq = W3s + c * 257;
        float s0 = __ldg(&B3[c]), s1 = 0.f;
        #pragma unroll 4
        for (int k = 0; k < 256; k += 2) {
            s0 = fmaf(dp[k],     wq[k],     s0);
            s1 = fmaf(dp[k + 1], wq[k + 1], s1);
        }
        out[row0 * 9 + e] = s0 + s1;
    }
}

// ---------------------------------------------------------------------------
__global__ void k_final(float* __restrict__ out) {
    __shared__ double sd[1024];
    __shared__ double mse_tot;
    int tid = threadIdx.x;
    double lm = 0.0;
    for (int i = tid; i < GRID; i += 1024) lm += (double)g_msep[i];
    sd[tid] = lm;
    __syncthreads();
    for (int o = 512; o; o >>= 1) {
        if (tid < o) sd[tid] += sd[tid + o];
        __syncthreads();
    }
    if (tid == 0) mse_tot = sd[0];
    __syncthreads();
    // entropy of code usage histogram (fp32 math matching reference)
    float p = (float)g_hist[tid] / 262144.0f;
    float term = p * logf(p + 1e-10f);
    sd[tid] = (double)term;
    __syncthreads();
    for (int o = 512; o; o >>= 1) {
        if (tid < o) sd[tid] += sd[tid + o];
        __syncthreads();
    }
    if (tid == 0) {
        float mse_mean = (float)(mse_tot / (262144.0 * 64.0));
        float vq_loss = 1.25f * mse_mean;   // q_latent + beta*e_latent, equal values
        float perp = expf(-(float)sd[0]);
        out[262144 * 9 + 0] = vq_loss;
        out[262144 * 9 + 1] = perp;
    }
}

// ---------------------------------------------------------------------------
extern "C" void kernel_launch(void* const* d_in, const int* in_sizes, int n_in,
                              void* d_out, int out_size) {
    const float* x   = (const float*)d_in[0];
    const float* ew1 = (const float*)d_in[1];
    const float* eb1 = (const float*)d_in[2];
    const float* ew2 = (const float*)d_in[3];
    const float* eb2 = (const float*)d_in[4];
    const float* ew3 = (const float*)d_in[5];
    const float* eb3 = (const float*)d_in[6];
    const float* dw1 = (const float*)d_in[7];
    const float* db1 = (const float*)d_in[8];
    const float* dw2 = (const float*)d_in[9];
    const float* db2 = (const float*)d_in[10];
    const float* dw3 = (const float*)d_in[11];
    const float* db3 = (const float*)d_in[12];
    const float* cb  = (const float*)d_in[13];
    float* out = (float*)d_out;

    void *p_h1, *p_h2, *p_q;
    cudaGetSymbolAddress(&p_h1, g_h1);
    cudaGetSymbolAddress(&p_h2, g_h2);
    cudaGetSymbolAddress(&p_q,  g_q);
    float* h1 = (float*)p_h1;
    float* h2 = (float*)p_h2;
    float* q  = (float*)p_q;

    const int SM_ENC2 = (64 * 257 + 128 * 257) * 4;          // 197376
    const int SM_DEC1 = (64 * 65 + 128 * 65) * 4;            // 49920
    const int SM_VQ   = (64*129 + 64*129 + 64*65 + 128*65 + 128 + 64*16*2 + 64) * 4; // 124928
    const int SM_D23  = (41280 + 9 * 257 + 16) * 4;          // 174436

    cudaFuncSetAttribute(k_mlp<256, 128, true>, cudaFuncAttributeMaxDynamicSharedMemorySize, SM_ENC2);
    cudaFuncSetAttribute(k_mlp<64, 128, true>,  cudaFuncAttributeMaxDynamicSharedMemorySize, SM_DEC1);
    cudaFuncSetAttribute(k_vq,    cudaFuncAttributeMaxDynamicSharedMemorySize, SM_VQ);
    cudaFuncSetAttribute(k_dec23, cudaFuncAttributeMaxDynamicSharedMemorySize, SM_D23);

    k_init<<<1, 1024>>>();
    k_hn<<<4, 256>>>(cb);
    k_enc1<<<GRID, 512>>>(x, ew1, eb1, h1);
    k_mlp<256, 128, true><<<GRID, 512, SM_ENC2>>>(h1, ew2, eb2, h2);
    k_vq<<<GRID, 512, SM_VQ>>>(h2, ew3, eb3, cb, q);
    k_mlp<64, 128, true><<<GRID, 512, SM_DEC1>>>(q, dw1, db1, h2);
    k_dec23<<<GRID, 512, SM_D23>>>(h2, dw2, db2, dw3, db3, out);
    k_final<<<1, 1024>>>(out);
}